// round 4
// baseline (speedup 1.0000x reference)
#include <cuda_runtime.h>
#include <cstdint>
#include <cstddef>

#define I_DIM 512
#define O_DIM 512
#define KDIM  4096          // I_DIM * 8 degrees
#define TILE_M 256
#define TILE_N 128
#define KC     32           // K per chunk (4 i's x 8 degrees)
#define NCHUNK (KDIM / KC)  // 128
#define THREADS 256
#define PITCH  144          // bytes per k-row in smem (32 words + 4 pad words)

// Transposed, tf32-rounded coefficients: Wt[o][k], k = i*8 + d
__device__ __align__(16) float g_Wt[(size_t)O_DIM * KDIM];

// ---------------- helpers ----------------
__device__ __forceinline__ uint32_t smem_u32(const void* p) {
    uint32_t a;
    asm("{ .reg .u64 t; cvta.to.shared.u64 t, %1; cvt.u32.u64 %0, t; }"
        : "=r"(a) : "l"(p));
    return a;
}

__device__ __forceinline__ uint32_t f2tf32(float f) {
    uint32_t r;
    asm("cvt.rna.tf32.f32 %0, %1;" : "=r"(r) : "f"(f));
    return r;
}

__device__ __forceinline__ uint32_t lds32(uint32_t a) {
    uint32_t v;
    asm volatile("ld.shared.b32 %0, [%1];" : "=r"(v) : "r"(a));
    return v;
}

__device__ __forceinline__ void sts128(uint32_t a, uint32_t v0, uint32_t v1,
                                       uint32_t v2, uint32_t v3) {
    asm volatile("st.shared.v4.b32 [%0], {%1,%2,%3,%4};"
                 :: "r"(a), "r"(v0), "r"(v1), "r"(v2), "r"(v3) : "memory");
}

__device__ __forceinline__ void mma8(float* c, const uint32_t* a, const uint32_t* b) {
    asm volatile(
        "mma.sync.aligned.m16n8k8.row.col.f32.tf32.tf32.f32 "
        "{%0,%1,%2,%3}, {%4,%5,%6,%7}, {%8,%9}, {%0,%1,%2,%3};"
        : "+f"(c[0]), "+f"(c[1]), "+f"(c[2]), "+f"(c[3])
        : "r"(a[0]), "r"(a[1]), "r"(a[2]), "r"(a[3]), "r"(b[0]), "r"(b[1]));
}

// accurate-enough tanh: 1 - 2/(exp(2x)+1); MUFU ex2 + approx div, err ~1e-6
__device__ __forceinline__ float fast_tanh(float x) {
    float e = __expf(2.0f * x);
    return 1.0f - __fdividef(2.0f, e + 1.0f);
}

// ---------------- kernel 0: transpose + tf32-round coeffs ----------------
// coeffs layout (i, o, d), d fastest. Writes Wt[o][i*8+d].
__global__ void prep_kernel(const float* __restrict__ coeffs) {
    int idx = blockIdx.x * blockDim.x + threadIdx.x;   // coalesced read
    int i = idx >> 12;
    int o = (idx >> 3) & 511;
    int d = idx & 7;
    reinterpret_cast<uint32_t*>(g_Wt)[(size_t)o * KDIM + i * 8 + d] =
        f2tf32(coeffs[idx]);
}

// ---------------- kernel 1: fused poly + mma.sync tf32 GEMM ----------------
// SMEM: A0 [0,36864) A1 [36864,73728) B0 [73728,92160) B1 [92160,110592)
#define SA0 0u
#define SA1 36864u
#define SB0 73728u
#define SB1 92160u
#define SMEM_BYTES 110592

__global__ void __launch_bounds__(THREADS, 1)
gegen_kernel(const float* __restrict__ x, float* __restrict__ out) {
    extern __shared__ __align__(16) char smem[];
    const uint32_t sb = smem_u32(smem);
    const int tid  = threadIdx.x;
    const int lane = tid & 31;
    const int wid  = tid >> 5;
    const int b0 = blockIdx.x * TILE_M;
    const int o0 = blockIdx.y * TILE_N;
    const int wm = (wid & 3) * 64;     // warp m offset
    const int wn = (wid >> 2) * 64;    // warp n offset

    float acc[4][8][4];
#pragma unroll
    for (int mf = 0; mf < 4; mf++)
#pragma unroll
        for (int nf = 0; nf < 8; nf++)
#pragma unroll
            for (int j = 0; j < 4; j++) acc[mf][nf][j] = 0.0f;

    // producer bases
    const float* xrow = x + (size_t)(b0 + tid) * I_DIM;          // one m-row/thread
    const float* wrow = g_Wt + (size_t)(o0 + (tid >> 1)) * KDIM + (tid & 1) * 16;
    const uint32_t a_sts = tid * PITCH;                           // + ii*32 (+16)
    const uint32_t b_sts = (tid >> 1) * PITCH + (tid & 1) * 64;   // + jj*16

    // ---- produce chunk c into (aBuf, bBuf); xv holds x[c*4 .. c*4+3] ----
    auto produce = [&](int c, uint32_t aBuf, uint32_t bBuf, float4 xv) {
        const float* src = wrow + c * KC;
#pragma unroll
        for (int jj = 0; jj < 4; jj++) {
            asm volatile("cp.async.cg.shared.global [%0], [%1], 16;"
                         :: "r"(bBuf + b_sts + jj * 16), "l"(src + jj * 4)
                         : "memory");
        }
        const float* xp = &xv.x;
#pragma unroll
        for (int ii = 0; ii < 4; ii++) {
            float t  = fast_tanh(xp[ii]);
            float t2 = t + t;
            float cm = 1.0f, cn = t2;
            uint32_t u[8];
            u[0] = 0x3f800000u;
            u[1] = f2tf32(cn);
#pragma unroll
            for (int n = 2; n < 8; n++) {
                float cx = fmaf(t2, cn, -cm);
                cm = cn; cn = cx;
                u[n] = f2tf32(cn);
            }
            uint32_t base = aBuf + a_sts + ii * 32;
            sts128(base,      u[0], u[1], u[2], u[3]);
            sts128(base + 16, u[4], u[5], u[6], u[7]);
        }
    };

    // ---- consume chunk from (aBuf, bBuf) ----
    auto consume = [&](uint32_t aBuf, uint32_t bBuf) {
#pragma unroll
        for (int ks = 0; ks < 4; ks++) {
            uint32_t a[4][4], b[8][2];
            const uint32_t koff = (ks * 8 + (lane & 3)) * 4;
#pragma unroll
            for (int mf = 0; mf < 4; mf++) {
                uint32_t base = aBuf + (wm + mf * 16 + (lane >> 2)) * PITCH + koff;
                a[mf][0] = lds32(base);
                a[mf][1] = lds32(base + 8 * PITCH);
                a[mf][2] = lds32(base + 16);
                a[mf][3] = lds32(base + 8 * PITCH + 16);
            }
#pragma unroll
            for (int nf = 0; nf < 8; nf++) {
                uint32_t base = bBuf + (wn + nf * 8 + (lane >> 2)) * PITCH + koff;
                b[nf][0] = lds32(base);
                b[nf][1] = lds32(base + 16);
            }
#pragma unroll
            for (int mf = 0; mf < 4; mf++)
#pragma unroll
                for (int nf = 0; nf < 8; nf++)
                    mma8(acc[mf][nf], a[mf], b[nf]);
        }
    };

    // ---- pipelined main loop ----
    float4 xv0 = *reinterpret_cast<const float4*>(xrow);           // chunk 0
    produce(0, sb + SA0, sb + SB0, xv0);
    asm volatile("cp.async.commit_group;" ::: "memory");
    float4 xreg = *reinterpret_cast<const float4*>(xrow + 4);      // chunk 1

#pragma unroll 1
    for (int c = 0; c < NCHUNK; c++) {
        const int s = c & 1;
        const uint32_t aCur = sb + (s ? SA1 : SA0);
        const uint32_t bCur = sb + (s ? SB1 : SB0);
        if (c + 1 < NCHUNK) {
            float4 xn;
            if (c + 2 < NCHUNK)                                    // prefetch c+2
                xn = *reinterpret_cast<const float4*>(xrow + (c + 2) * 4);
            produce(c + 1, sb + (s ? SA0 : SA1), sb + (s ? SB0 : SB1), xreg);
            asm volatile("cp.async.commit_group;" ::: "memory");
            asm volatile("cp.async.wait_group 1;" ::: "memory");
            if (c + 2 < NCHUNK) xreg = xn;
        } else {
            asm volatile("cp.async.wait_group 0;" ::: "memory");
        }
        __syncthreads();
        consume(aCur, bCur);
        __syncthreads();
    }

    // ---- epilogue: direct STG.64 ----
#pragma unroll
    for (int mf = 0; mf < 4; mf++) {
        const int rbase = b0 + wm + mf * 16 + (lane >> 2);
#pragma unroll
        for (int h = 0; h < 2; h++) {
            float* op = out + (size_t)(rbase + h * 8) * O_DIM
                            + o0 + wn + (lane & 3) * 2;
#pragma unroll
            for (int nf = 0; nf < 8; nf++) {
                float2 v;
                v.x = acc[mf][nf][h * 2];
                v.y = acc[mf][nf][h * 2 + 1];
                *reinterpret_cast<float2*>(op + nf * 8) = v;
            }
        }
    }
}

// ---------------- launch ----------------
extern "C" void kernel_launch(void* const* d_in, const int* in_sizes, int n_in,
                              void* d_out, int out_size) {
    const float* x      = (const float*)d_in[0];
    const float* coeffs = (const float*)d_in[1];
    float* out          = (float*)d_out;

    const int B = in_sizes[0] / I_DIM;   // 16384

    prep_kernel<<<(I_DIM * O_DIM * 8) / 256, 256>>>(coeffs);

    static int attr_set = 0;
    cudaFuncSetAttribute(gegen_kernel,
                         cudaFuncAttributeMaxDynamicSharedMemorySize, SMEM_BYTES);
    (void)attr_set;

    dim3 grid(B / TILE_M, O_DIM / TILE_N);
    gegen_kernel<<<grid, THREADS, SMEM_BYTES>>>(x, out);
}

// round 5
// speedup vs baseline: 1.1447x; 1.1447x over previous
#include <cuda_runtime.h>
#include <cstdint>
#include <cstddef>

#define I_DIM 512
#define O_DIM 512
#define KDIM  4096          // I_DIM * 8 degrees
#define TILE_M 256
#define TILE_N 128
#define KC     32           // K per chunk (4 i's x 8 degrees)
#define NCHUNK (KDIM / KC)  // 128
#define THREADS 256
#define PITCH  144          // bytes per k-row in smem (32 words + 4 pad words)

// Transposed, tf32-rounded coefficients: Wt[o][k], k = i*8 + d
__device__ __align__(16) float g_Wt[(size_t)O_DIM * KDIM];

// ---------------- helpers ----------------
__device__ __forceinline__ uint32_t smem_u32(const void* p) {
    uint32_t a;
    asm("{ .reg .u64 t; cvta.to.shared.u64 t, %1; cvt.u32.u64 %0, t; }"
        : "=r"(a) : "l"(p));
    return a;
}

__device__ __forceinline__ uint32_t f2tf32(float f) {
    uint32_t r;
    asm("cvt.rna.tf32.f32 %0, %1;" : "=r"(r) : "f"(f));
    return r;
}

__device__ __forceinline__ uint32_t lds32(uint32_t a) {
    uint32_t v;
    asm volatile("ld.shared.b32 %0, [%1];" : "=r"(v) : "r"(a));
    return v;
}

__device__ __forceinline__ void sts128(uint32_t a, uint32_t v0, uint32_t v1,
                                       uint32_t v2, uint32_t v3) {
    asm volatile("st.shared.v4.b32 [%0], {%1,%2,%3,%4};"
                 :: "r"(a), "r"(v0), "r"(v1), "r"(v2), "r"(v3) : "memory");
}

__device__ __forceinline__ void mma8(float* c, const uint32_t* a, const uint32_t* b) {
    asm volatile(
        "mma.sync.aligned.m16n8k8.row.col.f32.tf32.tf32.f32 "
        "{%0,%1,%2,%3}, {%4,%5,%6,%7}, {%8,%9}, {%0,%1,%2,%3};"
        : "+f"(c[0]), "+f"(c[1]), "+f"(c[2]), "+f"(c[3])
        : "r"(a[0]), "r"(a[1]), "r"(a[2]), "r"(a[3]), "r"(b[0]), "r"(b[1]));
}

// accurate-enough tanh: 1 - 2/(exp(2x)+1); MUFU ex2 + approx div, err ~1e-6
__device__ __forceinline__ float fast_tanh(float x) {
    float e = __expf(2.0f * x);
    return 1.0f - __fdividef(2.0f, e + 1.0f);
}

// ---------------- kernel 0: transpose + tf32-round coeffs ----------------
// coeffs layout (i, o, d), d fastest. Writes Wt[o][i*8+d].
__global__ void prep_kernel(const float* __restrict__ coeffs) {
    int idx = blockIdx.x * blockDim.x + threadIdx.x;   // coalesced read
    int i = idx >> 12;
    int o = (idx >> 3) & 511;
    int d = idx & 7;
    reinterpret_cast<uint32_t*>(g_Wt)[(size_t)o * KDIM + i * 8 + d] =
        f2tf32(coeffs[idx]);
}

// ---------------- kernel 1: fused poly + mma.sync tf32 GEMM ----------------
// Triple-buffered: A_s = 36864 B each, B_s = 18432 B each.
#define A_STRIDE 36864u
#define B_STRIDE 18432u
#define B_BASE   (3u * A_STRIDE)          // 110592
#define SMEM_BYTES (3 * (36864 + 18432)) // 165888

__global__ void __launch_bounds__(THREADS, 1)
gegen_kernel(const float* __restrict__ x, float* __restrict__ out) {
    extern __shared__ __align__(16) char smem[];
    const uint32_t sb = smem_u32(smem);
    const int tid  = threadIdx.x;
    const int lane = tid & 31;
    const int wid  = tid >> 5;
    const int b0 = blockIdx.x * TILE_M;
    const int o0 = blockIdx.y * TILE_N;
    const int wm = (wid & 3) * 64;     // warp m offset
    const int wn = (wid >> 2) * 64;    // warp n offset

    uint32_t aBase[3], bBase[3];
#pragma unroll
    for (int s = 0; s < 3; s++) {
        aBase[s] = sb + s * A_STRIDE;
        bBase[s] = sb + B_BASE + s * B_STRIDE;
    }

    float acc[4][8][4];
#pragma unroll
    for (int mf = 0; mf < 4; mf++)
#pragma unroll
        for (int nf = 0; nf < 8; nf++)
#pragma unroll
            for (int j = 0; j < 4; j++) acc[mf][nf][j] = 0.0f;

    // producer bases
    const float* xrow = x + (size_t)(b0 + tid) * I_DIM;          // one m-row/thread
    const float* wrow = g_Wt + (size_t)(o0 + (tid >> 1)) * KDIM + (tid & 1) * 16;
    const uint32_t a_sts = tid * PITCH;                           // + ii*32 (+16)
    const uint32_t b_sts = (tid >> 1) * PITCH + (tid & 1) * 64;   // + jj*16

    // ---- produce chunk c into (aBuf, bBuf); xv holds x[c*4 .. c*4+3] ----
    auto produce = [&](int c, uint32_t aBuf, uint32_t bBuf, float4 xv) {
        const float* src = wrow + c * KC;
#pragma unroll
        for (int jj = 0; jj < 4; jj++) {
            asm volatile("cp.async.cg.shared.global [%0], [%1], 16;"
                         :: "r"(bBuf + b_sts + jj * 16), "l"(src + jj * 4)
                         : "memory");
        }
        const float* xp = &xv.x;
#pragma unroll
        for (int ii = 0; ii < 4; ii++) {
            float t  = fast_tanh(xp[ii]);
            float t2 = t + t;
            float cm = 1.0f, cn = t2;
            uint32_t u[8];
            u[0] = 0x3f800000u;
            u[1] = f2tf32(cn);
#pragma unroll
            for (int n = 2; n < 8; n++) {
                float cx = fmaf(t2, cn, -cm);
                cm = cn; cn = cx;
                u[n] = f2tf32(cn);
            }
            uint32_t base = aBuf + a_sts + ii * 32;
            sts128(base,      u[0], u[1], u[2], u[3]);
            sts128(base + 16, u[4], u[5], u[6], u[7]);
        }
    };

    // ---- consume chunk from (aBuf, bBuf) ----
    auto consume = [&](uint32_t aBuf, uint32_t bBuf) {
#pragma unroll
        for (int ks = 0; ks < 4; ks++) {
            uint32_t a[4][4], b[8][2];
            const uint32_t koff = (ks * 8 + (lane & 3)) * 4;
#pragma unroll
            for (int mf = 0; mf < 4; mf++) {
                uint32_t base = aBuf + (wm + mf * 16 + (lane >> 2)) * PITCH + koff;
                a[mf][0] = lds32(base);
                a[mf][1] = lds32(base + 8 * PITCH);
                a[mf][2] = lds32(base + 16);
                a[mf][3] = lds32(base + 8 * PITCH + 16);
            }
#pragma unroll
            for (int nf = 0; nf < 8; nf++) {
                uint32_t base = bBuf + (wn + nf * 8 + (lane >> 2)) * PITCH + koff;
                b[nf][0] = lds32(base);
                b[nf][1] = lds32(base + 16);
            }
#pragma unroll
            for (int mf = 0; mf < 4; mf++)
#pragma unroll
                for (int nf = 0; nf < 8; nf++)
                    mma8(acc[mf][nf], a[mf], b[nf]);
        }
    };

    // ---- prologue: fill pipeline 2 deep ----
    float4 xv0 = *reinterpret_cast<const float4*>(xrow);
    produce(0, aBase[0], bBase[0], xv0);
    asm volatile("cp.async.commit_group;" ::: "memory");
    float4 xv1 = *reinterpret_cast<const float4*>(xrow + 4);
    produce(1, aBase[1], bBase[1], xv1);
    asm volatile("cp.async.commit_group;" ::: "memory");
    float4 xreg = *reinterpret_cast<const float4*>(xrow + 8);     // for chunk 2

    // ---- main loop: ONE barrier per chunk, produce/consume share the region ----
#pragma unroll 1
    for (int c = 0; c < NCHUNK; c++) {
        if (c + 1 < NCHUNK) {
            asm volatile("cp.async.wait_group 1;" ::: "memory");  // chunk c arrived
        } else {
            asm volatile("cp.async.wait_group 0;" ::: "memory");
        }
        __syncthreads();   // chunk c fully visible; buf (c+2)%3 free to overwrite

        const int cur = c % 3;
        consume(aBase[cur], bBase[cur]);

        if (c + 2 < NCHUNK) {
            const int nxt = (c + 2) % 3;
            produce(c + 2, aBase[nxt], bBase[nxt], xreg);
            asm volatile("cp.async.commit_group;" ::: "memory");
            if (c + 3 < NCHUNK)
                xreg = *reinterpret_cast<const float4*>(xrow + (c + 3) * 4);
        }
    }

    // ---- epilogue: direct STG.64 ----
#pragma unroll
    for (int mf = 0; mf < 4; mf++) {
        const int rbase = b0 + wm + mf * 16 + (lane >> 2);
#pragma unroll
        for (int h = 0; h < 2; h++) {
            float* op = out + (size_t)(rbase + h * 8) * O_DIM
                            + o0 + wn + (lane & 3) * 2;
#pragma unroll
            for (int nf = 0; nf < 8; nf++) {
                float2 v;
                v.x = acc[mf][nf][h * 2];
                v.y = acc[mf][nf][h * 2 + 1];
                *reinterpret_cast<float2*>(op + nf * 8) = v;
            }
        }
    }
}

// ---------------- launch ----------------
extern "C" void kernel_launch(void* const* d_in, const int* in_sizes, int n_in,
                              void* d_out, int out_size) {
    const float* x      = (const float*)d_in[0];
    const float* coeffs = (const float*)d_in[1];
    float* out          = (float*)d_out;

    const int B = in_sizes[0] / I_DIM;   // 16384

    prep_kernel<<<(I_DIM * O_DIM * 8) / 256, 256>>>(coeffs);

    cudaFuncSetAttribute(gegen_kernel,
                         cudaFuncAttributeMaxDynamicSharedMemorySize, SMEM_BYTES);

    dim3 grid(B / TILE_M, O_DIM / TILE_N);
    gegen_kernel<<<grid, THREADS, SMEM_BYTES>>>(x, out);
}

// round 6
// speedup vs baseline: 1.9613x; 1.7135x over previous
#include <cuda_runtime.h>
#include <cuda_fp16.h>
#include <cstdint>
#include <cstddef>

#define I_DIM 512
#define O_DIM 512
#define KDIM  4096          // I_DIM * 8 degrees
#define TILE_M 256
#define TILE_N 128
#define KC     64           // K elems per chunk (8 i's x 8 degrees)
#define NCHUNK (KDIM / KC)  // 64
#define THREADS 256
#define PITCH  272          // bytes per row in smem: 64 halves (128B) + 144B pad -> 68 words

#define COEF_SCALE   1024.0f
#define OUT_SCALE    (1.0f / 1024.0f)

// Transposed, scaled fp16 coefficients: Wh[o][k], k = i*8 + d
__device__ __align__(16) __half g_Wh[(size_t)O_DIM * KDIM];

// ---------------- helpers ----------------
__device__ __forceinline__ uint32_t smem_u32(const void* p) {
    uint32_t a;
    asm("{ .reg .u64 t; cvta.to.shared.u64 t, %1; cvt.u32.u64 %0, t; }"
        : "=r"(a) : "l"(p));
    return a;
}

__device__ __forceinline__ uint32_t lds32(uint32_t a) {
    uint32_t v;
    asm volatile("ld.shared.b32 %0, [%1];" : "=r"(v) : "r"(a));
    return v;
}

__device__ __forceinline__ void sts128(uint32_t a, uint32_t v0, uint32_t v1,
                                       uint32_t v2, uint32_t v3) {
    asm volatile("st.shared.v4.b32 [%0], {%1,%2,%3,%4};"
                 :: "r"(a), "r"(v0), "r"(v1), "r"(v2), "r"(v3) : "memory");
}

// m16n8k16 fp16 MMA, f32 accumulate
__device__ __forceinline__ void mma16(float* c, const uint32_t* a, const uint32_t* b) {
    asm volatile(
        "mma.sync.aligned.m16n8k16.row.col.f32.f16.f16.f32 "
        "{%0,%1,%2,%3}, {%4,%5,%6,%7}, {%8,%9}, {%0,%1,%2,%3};"
        : "+f"(c[0]), "+f"(c[1]), "+f"(c[2]), "+f"(c[3])
        : "r"(a[0]), "r"(a[1]), "r"(a[2]), "r"(a[3]), "r"(b[0]), "r"(b[1]));
}

__device__ __forceinline__ uint32_t pack_h2(float lo, float hi) {
    __half2 h = __floats2half2_rn(lo, hi);
    return *reinterpret_cast<uint32_t*>(&h);
}

// accurate-enough tanh: 1 - 2/(exp(2x)+1); MUFU-based, err ~1e-6
__device__ __forceinline__ float fast_tanh(float x) {
    float e = __expf(2.0f * x);
    return 1.0f - __fdividef(2.0f, e + 1.0f);
}

// ---------------- kernel 0: transpose + scale coeffs to fp16 ----------------
// coeffs layout (i, o, d), d fastest -> Wh[o][i*8+d] = coeff * 1024
__global__ void prep_kernel(const float* __restrict__ coeffs) {
    int idx = blockIdx.x * blockDim.x + threadIdx.x;   // coalesced read
    int i = idx >> 12;
    int o = (idx >> 3) & 511;
    int d = idx & 7;
    g_Wh[((size_t)o << 12) + (i << 3) + d] =
        __float2half_rn(coeffs[idx] * COEF_SCALE);
}

// ---------------- kernel 1: fused poly + fp16 mma GEMM ----------------
// Double-buffered: A stage = 256*272 = 69632 B, B stage = 128*272 = 34816 B
#define A_STRIDE 69632u
#define B_STRIDE 34816u
#define B_BASE   (2u * A_STRIDE)
#define SMEM_BYTES (2 * (69632 + 34816))   // 208896

__global__ void __launch_bounds__(THREADS, 1)
gegen_kernel(const float* __restrict__ x, float* __restrict__ out) {
    extern __shared__ __align__(16) char smem[];
    const uint32_t sb = smem_u32(smem);
    const int tid  = threadIdx.x;
    const int lane = tid & 31;
    const int wid  = tid >> 5;
    const int b0 = blockIdx.x * TILE_M;
    const int o0 = blockIdx.y * TILE_N;
    const int wm = (wid & 3) * 64;     // warp m offset
    const int wn = (wid >> 2) * 64;    // warp n offset

    uint32_t aBase[2], bBase[2];
#pragma unroll
    for (int s = 0; s < 2; s++) {
        aBase[s] = sb + s * A_STRIDE;
        bBase[s] = sb + B_BASE + s * B_STRIDE;
    }

    float acc[4][8][4];
#pragma unroll
    for (int mf = 0; mf < 4; mf++)
#pragma unroll
        for (int nf = 0; nf < 8; nf++)
#pragma unroll
            for (int j = 0; j < 4; j++) acc[mf][nf][j] = 0.0f;

    // producer bases
    const float* xrow = x + (size_t)(b0 + tid) * I_DIM;            // one m-row/thread
    const __half* wrow = g_Wh + ((size_t)(o0 + (tid >> 1)) << 12)  // o-row
                       + (tid & 1) * 32;                           // half-row in halves
    const uint32_t a_sts = tid * PITCH;
    const uint32_t b_sts = (tid >> 1) * PITCH + (tid & 1) * 64;    // + j*16

    // ---- produce chunk c into buffers; xv8 = x[c*8 .. c*8+7] ----
    auto produce = [&](int c, uint32_t aBuf, uint32_t bBuf,
                       const float4& x0, const float4& x1) {
        // B tile: 4 x 16B cp.async per thread (row = tid>>1, 64B half-row)
        const __half* src = wrow + c * KC;
#pragma unroll
        for (int j = 0; j < 4; j++) {
            asm volatile("cp.async.cg.shared.global [%0], [%1], 16;"
                         :: "r"(bBuf + b_sts + j * 16), "l"(src + j * 8)
                         : "memory");
        }
        // A tile: 8 i's -> 8 polys each -> fp16 pairs -> 8 x sts128
        const float xv[8] = {x0.x, x0.y, x0.z, x0.w, x1.x, x1.y, x1.z, x1.w};
#pragma unroll
        for (int ii = 0; ii < 8; ii++) {
            float t  = fast_tanh(xv[ii]);
            float t2 = t + t;
            float c0 = 1.0f, c1 = t2;
            float c2 = fmaf(t2, c1, -c0);
            float c3 = fmaf(t2, c2, -c1);
            float c4 = fmaf(t2, c3, -c2);
            float c5 = fmaf(t2, c4, -c3);
            float c6 = fmaf(t2, c5, -c4);
            float c7 = fmaf(t2, c6, -c5);
            sts128(aBuf + a_sts + ii * 16,
                   pack_h2(c0, c1), pack_h2(c2, c3),
                   pack_h2(c4, c5), pack_h2(c6, c7));
        }
    };

    // ---- consume one chunk with k-step fragment double-buffering ----
    auto loadA = [&](uint32_t aBuf, int ks, uint32_t a[4][4]) {
        const uint32_t koff = ks * 32 + (lane & 3) * 4;
#pragma unroll
        for (int mf = 0; mf < 4; mf++) {
            uint32_t base = aBuf + (wm + mf * 16 + (lane >> 2)) * PITCH + koff;
            a[mf][0] = lds32(base);
            a[mf][1] = lds32(base + 8 * PITCH);
            a[mf][2] = lds32(base + 16);
            a[mf][3] = lds32(base + 8 * PITCH + 16);
        }
    };
    auto loadB = [&](uint32_t bBuf, int ks, uint32_t b[8][2]) {
        const uint32_t koff = ks * 32 + (lane & 3) * 4;
#pragma unroll
        for (int nf = 0; nf < 8; nf++) {
            uint32_t base = bBuf + (wn + nf * 8 + (lane >> 2)) * PITCH + koff;
            b[nf][0] = lds32(base);
            b[nf][1] = lds32(base + 16);
        }
    };

    auto consume = [&](uint32_t aBuf, uint32_t bBuf) {
        uint32_t a[2][4][4], b[2][8][2];
        loadA(aBuf, 0, a[0]);
        loadB(bBuf, 0, b[0]);
#pragma unroll
        for (int ks = 0; ks < 4; ks++) {
            const int cur = ks & 1, nxt = cur ^ 1;
            if (ks < 3) {
                loadA(aBuf, ks + 1, a[nxt]);
                loadB(bBuf, ks + 1, b[nxt]);
            }
#pragma unroll
            for (int mf = 0; mf < 4; mf++)
#pragma unroll
                for (int nf = 0; nf < 8; nf++)
                    mma16(acc[mf][nf], a[cur][mf], b[cur][nf]);
        }
    };

    // ---- prologue ----
    float4 xa = *reinterpret_cast<const float4*>(xrow);
    float4 xb = *reinterpret_cast<const float4*>(xrow + 4);
    produce(0, aBase[0], bBase[0], xa, xb);
    asm volatile("cp.async.commit_group;" ::: "memory");
    xa = *reinterpret_cast<const float4*>(xrow + 8);      // chunk 1
    xb = *reinterpret_cast<const float4*>(xrow + 12);

    // ---- main loop: one barrier per chunk; produce(c+1) then consume(c) ----
#pragma unroll 1
    for (int c = 0; c < NCHUNK; c++) {
        asm volatile("cp.async.wait_group 0;" ::: "memory");
        __syncthreads();   // chunk c visible; buffer (c+1)&1 free (consume(c-1) done)

        if (c + 1 < NCHUNK) {
            produce(c + 1, aBase[(c + 1) & 1], bBase[(c + 1) & 1], xa, xb);
            asm volatile("cp.async.commit_group;" ::: "memory");
            if (c + 2 < NCHUNK) {
                xa = *reinterpret_cast<const float4*>(xrow + (c + 2) * 8);
                xb = *reinterpret_cast<const float4*>(xrow + (c + 2) * 8 + 4);
            }
        }
        consume(aBase[c & 1], bBase[c & 1]);
    }

    // ---- epilogue: scale back and store ----
#pragma unroll
    for (int mf = 0; mf < 4; mf++) {
        const int rbase = b0 + wm + mf * 16 + (lane >> 2);
#pragma unroll
        for (int h = 0; h < 2; h++) {
            float* op = out + (size_t)(rbase + h * 8) * O_DIM
                            + o0 + wn + (lane & 3) * 2;
#pragma unroll
            for (int nf = 0; nf < 8; nf++) {
                float2 v;
                v.x = acc[mf][nf][h * 2]     * OUT_SCALE;
                v.y = acc[mf][nf][h * 2 + 1] * OUT_SCALE;
                *reinterpret_cast<float2*>(op + nf * 8) = v;
            }
        }
    }
}

// ---------------- launch ----------------
extern "C" void kernel_launch(void* const* d_in, const int* in_sizes, int n_in,
                              void* d_out, int out_size) {
    const float* x      = (const float*)d_in[0];
    const float* coeffs = (const float*)d_in[1];
    float* out          = (float*)d_out;

    const int B = in_sizes[0] / I_DIM;   // 16384

    prep_kernel<<<(I_DIM * O_DIM * 8) / 256, 256>>>(coeffs);

    cudaFuncSetAttribute(gegen_kernel,
                         cudaFuncAttributeMaxDynamicSharedMemorySize, SMEM_BYTES);

    dim3 grid(B / TILE_M, O_DIM / TILE_N);
    gegen_kernel<<<grid, THREADS, SMEM_BYTES>>>(x, out);
}